// round 12
// baseline (speedup 1.0000x reference)
#include <cuda_runtime.h>
#include <cstdint>

#define NN   10000
#define EE   80000
#define ETOT 90000
#define FIN  128
#define D1   2048
#define H1   8
#define C1   256
#define D2   32

// ---------------- scratch (static __device__, no allocations) ----------------
__device__ float g_self[(size_t)NN * FIN];        // self-loop edge attrs (mean)
__device__ float g_xl1[(size_t)NN * D1];
__device__ float g_xr1[(size_t)NN * D1];
__device__ float g_h[(size_t)NN * D1];
__device__ float g_logits[(size_t)ETOT * H1];
__device__ float g_xl2[(size_t)NN * D2];
__device__ float g_xr2[(size_t)NN * D2];
__device__ float g_logits2[ETOT];
// fragment-order packed, tf32-rounded weight buffers
__device__ float g_Wl1hi[(size_t)FIN * D1];
__device__ float g_Wl1lo[(size_t)FIN * D1];
__device__ float g_Wr1hi[(size_t)FIN * D1];
__device__ float g_Wr1lo[(size_t)FIN * D1];
__device__ float g_We1p[(size_t)FIN * D1];
__device__ float g_W2hi[(size_t)D1 * 64];
__device__ float g_W2lo[(size_t)D1 * 64];
__device__ int   g_cnt[NN];
__device__ int   g_rowptr[NN + 1];
__device__ int   g_cursor[NN];
__device__ int   g_eids[EE];

__device__ __forceinline__ float to_tf32(float x) {
    float r;
    asm("cvt.rna.tf32.f32 %0, %1;" : "=f"(r) : "f"(x));
    return r;
}

__device__ __forceinline__ void mma_tf32(float* c,
                                         float a0, float a1, float a2, float a3,
                                         float b0, float b1)
{
    asm volatile(
        "mma.sync.aligned.m16n8k8.row.col.f32.tf32.tf32.f32 "
        "{%0,%1,%2,%3}, {%4,%5,%6,%7}, {%8,%9}, {%0,%1,%2,%3};"
        : "+f"(c[0]), "+f"(c[1]), "+f"(c[2]), "+f"(c[3])
        : "r"(__float_as_uint(a0)), "r"(__float_as_uint(a1)),
          "r"(__float_as_uint(a2)), "r"(__float_as_uint(a3)),
          "r"(__float_as_uint(b0)), "r"(__float_as_uint(b1)));
}

// ---------------- CSR construction ----------------
__global__ void zero_cnt_kernel() {
    int i = blockIdx.x * 256 + threadIdx.x;
    if (i < NN) g_cnt[i] = 0;
}

__global__ void count_kernel(const int* __restrict__ ei) {
    int e = blockIdx.x * 256 + threadIdx.x;
    if (e < EE) atomicAdd(&g_cnt[ei[EE + e]], 1);
}

__global__ void scan_kernel() {
    __shared__ int sd[1024];
    __shared__ int carry;
    int tid = threadIdx.x;
    if (tid == 0) carry = 0;
    __syncthreads();
    for (int base = 0; base < NN; base += 1024) {
        int i = base + tid;
        int v = (i < NN) ? g_cnt[i] : 0;
        sd[tid] = v;
        __syncthreads();
        for (int off = 1; off < 1024; off <<= 1) {
            int t = (tid >= off) ? sd[tid - off] : 0;
            __syncthreads();
            sd[tid] += t;
            __syncthreads();
        }
        int excl = sd[tid] - v + carry;
        if (i < NN) { g_rowptr[i] = excl; g_cursor[i] = excl; }
        __syncthreads();
        if (tid == 1023) carry += sd[1023];
        __syncthreads();
    }
    if (tid == 0) g_rowptr[NN] = carry;
}

__global__ void scatter_kernel(const int* __restrict__ ei) {
    int e = blockIdx.x * 256 + threadIdx.x;
    if (e < EE) {
        int d = ei[EE + e];
        int pos = atomicAdd(&g_cursor[d], 1);
        g_eids[pos] = e;
    }
}

// ---------------- self-loop attr = mean of incoming edge attrs ----------------
__global__ void selfattr_kernel(const float* __restrict__ ea) {
    int n = blockIdx.x;
    int tid = threadIdx.x;  // 128 threads = FIN
    int beg = g_rowptr[n], end = g_rowptr[n + 1];
    float s = 0.0f;
    for (int p = beg; p < end; p++)
        s += ea[(size_t)g_eids[p] * FIN + tid];
    float c = (float)((end - beg) > 1 ? (end - beg) : 1);
    g_self[(size_t)n * FIN + tid] = s / c;
}

// ---------------- fragment-order weight packing (device-side destinations) --------
// flat = ((((chunk*NW + wn)*4 + n)*8 + g)*4 + c)*4 + j  for k = chunk*16 + c + 4j,
// col = wn*32 + n*8 + g, NW = Ntot/32.
// dst: 0=We1p(hi only) 1=Wl1 2=Wr1 3=W2(colOff)
__global__ void pack_kernel(const float* __restrict__ W, int K, int Ntot,
                            int colOff, int Ncols, int dst)
{
    int i = blockIdx.x * 256 + threadIdx.x;
    if (i >= K * Ncols) return;
    int k = i / Ncols, cl = i % Ncols;
    int gc = colOff + cl;
    int chunk = k >> 4;
    int c = k & 3, j = (k & 15) >> 2;
    int wn = gc >> 5, n = (gc >> 3) & 3, g = gc & 7;
    size_t flat = ((((size_t)(chunk * (Ntot >> 5) + wn) * 4 + n) * 8 + g) * 4 + c) * 4 + j;
    float w = W[i];
    float h = to_tf32(w);
    float l = to_tf32(w - h);
    if (dst == 0)      { g_We1p[flat] = h; }
    else if (dst == 1) { g_Wl1hi[flat] = h; g_Wl1lo[flat] = l; }
    else if (dst == 2) { g_Wr1hi[flat] = h; g_Wr1lo[flat] = l; }
    else               { g_W2hi[flat] = h;  g_W2lo[flat] = l; }
}

// ---------------- layer-1 node projection, split-tf32 MMA, packed B (R6-exact) ----------
// BM=64, BN=128, K=128. grid.y in [0,32): y<16 -> Wl1 cols, y>=16 -> Wr1.
__global__ __launch_bounds__(256)
void proj1_tc(const float* __restrict__ x,
              const float* __restrict__ bl1, const float* __restrict__ br1)
{
    __shared__ float As[64 * 144];     // raw fp32, k-permuted + XOR-swizzled
    const int tid = threadIdx.x;
    const int lane = tid & 31;
    const int warp = tid >> 5;
    const int warp_m = warp & 1;
    const int warp_n = warp >> 1;
    const int g = lane >> 2;
    const int c = lane & 3;
    const int blockRow = blockIdx.x * 64;
    const int ymat = blockIdx.y >> 4;
    const int cbm = (blockIdx.y & 15) * 128;

    const float4* __restrict__ Bh = (const float4*)(ymat ? g_Wr1hi : g_Wl1hi);
    const float4* __restrict__ Bl = (const float4*)(ymat ? g_Wr1lo : g_Wl1lo);
    const float* __restrict__ bias = ymat ? br1 : bl1;
    float* __restrict__ C = ymat ? g_xr1 : g_xl1;

    {
        int row = tid >> 2;
        int gr = blockRow + row; if (gr > NN - 1) gr = NN - 1;
        const float4* ap = (const float4*)(x + (size_t)gr * FIN);
        int rs = row & 3;
        #pragma unroll
        for (int i = 0; i < 8; i++) {
            int q = (tid & 3) + i * 4;
            float4 v = ap[q];
            int base = row * 144 + i * 16 + (tid & 3);
            As[base + ((0 ^ rs) << 2)] = v.x;
            As[base + ((1 ^ rs) << 2)] = v.y;
            As[base + ((2 ^ rs) << 2)] = v.z;
            As[base + ((3 ^ rs) << 2)] = v.w;
        }
    }
    __syncthreads();

    float cc[2][4][4];
    #pragma unroll
    for (int m = 0; m < 2; m++)
        #pragma unroll
        for (int n = 0; n < 4; n++)
            #pragma unroll
            for (int j = 0; j < 4; j++) cc[m][n][j] = 0.0f;

    const int wn = (cbm >> 5) + warp_n;
    const int cswz = ((c ^ (g & 3)) << 2);

    #pragma unroll
    for (int chunk = 0; chunk < 8; chunk++) {
        float4 vh[2][2], vl[2][2];
        #pragma unroll
        for (int m = 0; m < 2; m++) {
            int col = (warp_m * 32 + m * 16 + g) * 144 + chunk * 16 + cswz;
            #pragma unroll
            for (int hh = 0; hh < 2; hh++) {
                float4 raw = *(const float4*)(As + col + hh * (8 * 144));
                float4 h, l;
                h.x = to_tf32(raw.x); l.x = to_tf32(raw.x - h.x);
                h.y = to_tf32(raw.y); l.y = to_tf32(raw.y - h.y);
                h.z = to_tf32(raw.z); l.z = to_tf32(raw.z - h.z);
                h.w = to_tf32(raw.w); l.w = to_tf32(raw.w - h.w);
                vh[m][hh] = h; vl[m][hh] = l;
            }
        }
        size_t base4 = ((size_t)(chunk * 64 + wn) * 32 + g) * 4 + c;
        float4 bh[4], bo[4];
        #pragma unroll
        for (int n = 0; n < 4; n++) {
            bh[n] = Bh[base4 + n * 32];
            bo[n] = Bl[base4 + n * 32];
        }
        #pragma unroll
        for (int n = 0; n < 4; n++) {
            #pragma unroll
            for (int m = 0; m < 2; m++) {
                mma_tf32(cc[m][n], vh[m][0].x, vh[m][1].x, vh[m][0].y, vh[m][1].y, bh[n].x, bh[n].y);
                mma_tf32(cc[m][n], vh[m][0].x, vh[m][1].x, vh[m][0].y, vh[m][1].y, bo[n].x, bo[n].y);
                mma_tf32(cc[m][n], vl[m][0].x, vl[m][1].x, vl[m][0].y, vl[m][1].y, bh[n].x, bh[n].y);
                mma_tf32(cc[m][n], vh[m][0].z, vh[m][1].z, vh[m][0].w, vh[m][1].w, bh[n].z, bh[n].w);
                mma_tf32(cc[m][n], vh[m][0].z, vh[m][1].z, vh[m][0].w, vh[m][1].w, bo[n].z, bo[n].w);
                mma_tf32(cc[m][n], vl[m][0].z, vl[m][1].z, vl[m][0].w, vl[m][1].w, bh[n].z, bh[n].w);
            }
        }
    }

    #pragma unroll
    for (int n = 0; n < 4; n++) {
        int col = cbm + warp_n * 32 + n * 8 + c * 2;
        float2 bv = *(const float2*)(bias + col);
        #pragma unroll
        for (int m = 0; m < 2; m++) {
            #pragma unroll
            for (int hh = 0; hh < 2; hh++) {
                int r = blockRow + warp_m * 32 + m * 16 + hh * 8 + g;
                if (r < NN) {
                    float2 o;
                    o.x = cc[m][n][hh * 2 + 0] + bv.x;
                    o.y = cc[m][n][hh * 2 + 1] + bv.y;
                    *(float2*)(C + (size_t)r * D1 + col) = o;
                }
            }
        }
    }
}

// ---------------- fused edge GEMM + GATv2 logits (layer 1) ----------------
// grid = (1407, 8): one head per block, loop over that head's 2 column blocks.
// Logits reduced block-locally (shuffle + smem) and stored once — no atomics.
__global__ __launch_bounds__(256)
void edge_logits1_tc(const float* __restrict__ ea, const int* __restrict__ ei,
                     const float* __restrict__ att)
{
    __shared__ float As[64 * 144];
    __shared__ float sm_red[4][64];    // [warp_n][row]
    const int tid = threadIdx.x;
    const int lane = tid & 31;
    const int warp = tid >> 5;
    const int warp_m = warp & 1;
    const int warp_n = warp >> 1;
    const int g = lane >> 2;
    const int c = lane & 3;
    const int blockRow = blockIdx.x * 64;
    const int head = blockIdx.y;

    {
        int row = tid >> 2;
        int ge = blockRow + row; if (ge > ETOT - 1) ge = ETOT - 1;
        const float4* ap = (ge < EE) ? (const float4*)(ea + (size_t)ge * FIN)
                                     : (const float4*)(g_self + (size_t)(ge - EE) * FIN);
        int rs = row & 3;
        #pragma unroll
        for (int i = 0; i < 8; i++) {
            int q = (tid & 3) + i * 4;
            float4 v = ap[q];
            int base = row * 144 + (q >> 2) * 16 + (q & 3);
            As[base + ((0 ^ rs) << 2)] = to_tf32(v.x);
            As[base + ((1 ^ rs) << 2)] = to_tf32(v.y);
            As[base + ((2 ^ rs) << 2)] = to_tf32(v.z);
            As[base + ((3 ^ rs) << 2)] = to_tf32(v.w);
        }
    }
    __syncthreads();

    // hoist per-(m,h) edge ids and src/dst
    int ges[2][2], srcs[2][2], dsts[2][2];
    bool valids[2][2];
    #pragma unroll
    for (int m = 0; m < 2; m++) {
        #pragma unroll
        for (int h = 0; h < 2; h++) {
            int ge = blockRow + warp_m * 32 + m * 16 + h * 8 + g;
            ges[m][h] = ge;
            valids[m][h] = (ge < ETOT);
            int s = 0, d = 0;
            if (ge < EE)       { s = ei[ge]; d = ei[EE + ge]; }
            else if (ge < ETOT){ s = d = ge - EE; }
            srcs[m][h] = s; dsts[m][h] = d;
        }
    }

    const int cswz = ((c ^ (g & 3)) << 2);
    const float4* __restrict__ Bp = (const float4*)g_We1p;

    float pacc[2][2] = {{0.0f, 0.0f}, {0.0f, 0.0f}};

    #pragma unroll
    for (int half = 0; half < 2; half++) {
        const int cbi = head * 2 + half;
        const int cb = cbi * 128;
        const int wn = cbi * 4 + warp_n;

        float cc[2][4][4];
        #pragma unroll
        for (int m = 0; m < 2; m++)
            #pragma unroll
            for (int n = 0; n < 4; n++)
                #pragma unroll
                for (int j = 0; j < 4; j++) cc[m][n][j] = 0.0f;

        #pragma unroll
        for (int chunk = 0; chunk < 8; chunk++) {
            float4 va[2][2];
            #pragma unroll
            for (int m = 0; m < 2; m++) {
                int col = (warp_m * 32 + m * 16 + g) * 144 + chunk * 16 + cswz;
                va[m][0] = *(const float4*)(As + col);
                va[m][1] = *(const float4*)(As + col + 8 * 144);
            }
            size_t base4 = ((size_t)(chunk * 64 + wn) * 32 + g) * 4 + c;
            float4 bf[4];
            #pragma unroll
            for (int n = 0; n < 4; n++)
                bf[n] = Bp[base4 + n * 32];
            #pragma unroll
            for (int n = 0; n < 4; n++) {
                #pragma unroll
                for (int m = 0; m < 2; m++) {
                    mma_tf32(cc[m][n], va[m][0].x, va[m][1].x, va[m][0].y, va[m][1].y, bf[n].x, bf[n].y);
                    mma_tf32(cc[m][n], va[m][0].z, va[m][1].z, va[m][0].w, va[m][1].w, bf[n].z, bf[n].w);
                }
            }
        }

        float2 attv[4];
        #pragma unroll
        for (int n = 0; n < 4; n++)
            attv[n] = *(const float2*)(att + cb + warp_n * 32 + n * 8 + c * 2);

        #pragma unroll
        for (int m = 0; m < 2; m++) {
            #pragma unroll
            for (int h = 0; h < 2; h++) {
                if (valids[m][h]) {
                    const float* xlp = g_xl1 + (size_t)srcs[m][h] * D1 + cb;
                    const float* xrp = g_xr1 + (size_t)dsts[m][h] * D1 + cb;
                    float p = pacc[m][h];
                    #pragma unroll
                    for (int n = 0; n < 4; n++) {
                        int cl = warp_n * 32 + n * 8 + c * 2;
                        float2 xv = *(const float2*)(xlp + cl);
                        float2 rv = *(const float2*)(xrp + cl);
                        float t0 = cc[m][n][h * 2 + 0] + xv.x + rv.x;
                        float t1 = cc[m][n][h * 2 + 1] + xv.y + rv.y;
                        t0 = (t0 > 0.f) ? t0 : 0.2f * t0;
                        t1 = (t1 > 0.f) ? t1 : 0.2f * t1;
                        p = fmaf(t0, attv[n].x, p);
                        p = fmaf(t1, attv[n].y, p);
                    }
                    pacc[m][h] = p;
                }
            }
        }
    }

    // block-local reduction: warp shuffle over c lanes, then cross-warp_n via smem
    #pragma unroll
    for (int m = 0; m < 2; m++) {
        #pragma unroll
        for (int h = 0; h < 2; h++) {
            float p = pacc[m][h];
            p += __shfl_xor_sync(0xffffffffu, p, 1);
            p += __shfl_xor_sync(0xffffffffu, p, 2);
            if (c == 0)
                sm_red[warp_n][warp_m * 32 + m * 16 + h * 8 + g] = p;
        }
    }
    __syncthreads();
    if (tid < 64) {
        int ge = blockRow + tid;
        if (ge < ETOT) {
            float p = sm_red[0][tid] + sm_red[1][tid]
                    + sm_red[2][tid] + sm_red[3][tid];
            g_logits[(size_t)ge * H1 + head] = p;
        }
    }
}

// ---------------- layer-1 segment softmax + aggregation + bias + relu ----------------
__global__ __launch_bounds__(256)
void agg1_kernel(const int* __restrict__ ei, const float* __restrict__ b1)
{
    const int n = blockIdx.x, tid = threadIdx.x;
    __shared__ float mx[H1], inv[H1];
    const int beg = g_rowptr[n], end = g_rowptr[n + 1];
    if (tid < H1) {
        float m = g_logits[(size_t)(EE + n) * H1 + tid];
        for (int p = beg; p < end; p++)
            m = fmaxf(m, g_logits[(size_t)g_eids[p] * H1 + tid]);
        float s = __expf(g_logits[(size_t)(EE + n) * H1 + tid] - m);
        for (int p = beg; p < end; p++)
            s += __expf(g_logits[(size_t)g_eids[p] * H1 + tid] - m);
        mx[tid] = m;
        inv[tid] = 1.0f / s;
    }
    __syncthreads();
    float acc[8];
    #pragma unroll
    for (int j = 0; j < 8; j++) acc[j] = 0.0f;
    for (int p = beg; p <= end; p++) {
        int e, s;
        if (p < end) { e = g_eids[p]; s = ei[e]; }
        else         { e = EE + n;    s = n; }
        const float* lr = g_logits + (size_t)e * H1;
        const float* xp = g_xl1 + (size_t)s * D1 + tid;
        #pragma unroll
        for (int j = 0; j < 8; j++) {
            float a = __expf(lr[j] - mx[j]) * inv[j];
            acc[j] = fmaf(a, xp[j * 256], acc[j]);
        }
    }
    #pragma unroll
    for (int j = 0; j < 8; j++) {
        int col = j * 256 + tid;
        g_h[(size_t)n * D1 + col] = fmaxf(acc[j] + b1[col], 0.0f);
    }
}

// ---------------- layer-2 projections, split-tf32 MMA, packed B ----------------
__global__ __launch_bounds__(256)
void proj2_tc(const float* __restrict__ bl2, const float* __restrict__ br2)
{
    __shared__ float As2[64 * 20];     // raw fp32, k-permuted
    const int tid = threadIdx.x;
    const int lane = tid & 31;
    const int warp = tid >> 5;
    const int warp_m = warp & 3;
    const int warp_n = warp >> 2;
    const int g = lane >> 2;
    const int c = lane & 3;
    const int blockRow = blockIdx.x * 64;

    const int arow = tid >> 2;
    const int aq = tid & 3;
    int gr = blockRow + arow; if (gr > NN - 1) gr = NN - 1;
    const float* aptr = g_h + (size_t)gr * D1 + aq * 4;

    const float4* __restrict__ Bh = (const float4*)g_W2hi;
    const float4* __restrict__ Bl = (const float4*)g_W2lo;

    float cc[4][4];
    #pragma unroll
    for (int n = 0; n < 4; n++)
        #pragma unroll
        for (int j = 0; j < 4; j++) cc[n][j] = 0.0f;

    float4 v = *(const float4*)(aptr);
    for (int chunk = 0; chunk < 128; chunk++) {
        As2[arow * 20 + 0 * 4 + aq] = v.x;
        As2[arow * 20 + 1 * 4 + aq] = v.y;
        As2[arow * 20 + 2 * 4 + aq] = v.z;
        As2[arow * 20 + 3 * 4 + aq] = v.w;
        __syncthreads();
        if (chunk < 127) v = *(const float4*)(aptr + (chunk + 1) * 16);

        float4 r0 = *(const float4*)(As2 + (warp_m * 16 + g) * 20 + c * 4);
        float4 r1 = *(const float4*)(As2 + (warp_m * 16 + g + 8) * 20 + c * 4);
        float4 h0, l0, h1, l1;
        h0.x = to_tf32(r0.x); l0.x = to_tf32(r0.x - h0.x);
        h0.y = to_tf32(r0.y); l0.y = to_tf32(r0.y - h0.y);
        h0.z = to_tf32(r0.z); l0.z = to_tf32(r0.z - h0.z);
        h0.w = to_tf32(r0.w); l0.w = to_tf32(r0.w - h0.w);
        h1.x = to_tf32(r1.x); l1.x = to_tf32(r1.x - h1.x);
        h1.y = to_tf32(r1.y); l1.y = to_tf32(r1.y - h1.y);
        h1.z = to_tf32(r1.z); l1.z = to_tf32(r1.z - h1.z);
        h1.w = to_tf32(r1.w); l1.w = to_tf32(r1.w - h1.w);

        size_t base4 = ((size_t)(chunk * 2 + warp_n) * 32 + g) * 4 + c;
        #pragma unroll
        for (int n = 0; n < 4; n++) {
            float4 bh = Bh[base4 + n * 32];
            float4 bo = Bl[base4 + n * 32];
            mma_tf32(cc[n], h0.x, h1.x, h0.y, h1.y, bh.x, bh.y);
            mma_tf32(cc[n], h0.x, h1.x, h0.y, h1.y, bo.x, bo.y);
            mma_tf32(cc[n], l0.x, l1.x, l0.y, l1.y, bh.x, bh.y);
            mma_tf32(cc[n], h0.z, h1.z, h0.w, h1.w, bh.z, bh.w);
            mma_tf32(cc[n], h0.z, h1.z, h0.w, h1.w, bo.z, bo.w);
            mma_tf32(cc[n], l0.z, l1.z, l0.w, l1.w, bh.z, bh.w);
        }
        __syncthreads();
    }

    #pragma unroll
    for (int n = 0; n < 4; n++) {
        int col = warp_n * 32 + n * 8 + c * 2;       // 0..63
        int lc = col & 31;
        const float* bias = (col < 32) ? bl2 : br2;
        float* C = (col < 32) ? g_xl2 : g_xr2;
        float2 bv = *(const float2*)(bias + lc);
        #pragma unroll
        for (int hh = 0; hh < 2; hh++) {
            int r = blockRow + warp_m * 16 + hh * 8 + g;
            if (r < NN) {
                float2 o;
                o.x = cc[n][hh * 2 + 0] + bv.x;
                o.y = cc[n][hh * 2 + 1] + bv.y;
                *(float2*)(C + (size_t)r * D2 + lc) = o;
            }
        }
    }
}

// ---------------- layer-2 edge logits ----------------
__global__ __launch_bounds__(128)
void edge_logits2_kernel(const float* __restrict__ ea, const int* __restrict__ ei,
                         const float* __restrict__ We2, const float* __restrict__ att2)
{
    __shared__ float sm[4][FIN];
    const int lane = threadIdx.x & 31, w = threadIdx.x >> 5;
    const int ge = blockIdx.x * 4 + w;
    if (ge >= ETOT) return;
    const float* arow = (ge < EE) ? (ea + (size_t)ge * FIN)
                                  : (g_self + (size_t)(ge - EE) * FIN);
    sm[w][lane]      = arow[lane];
    sm[w][lane + 32] = arow[lane + 32];
    sm[w][lane + 64] = arow[lane + 64];
    sm[w][lane + 96] = arow[lane + 96];
    __syncwarp();
    float acc = 0.0f;
    #pragma unroll 8
    for (int k = 0; k < FIN; k++)
        acc = fmaf(sm[w][k], We2[(size_t)k * D2 + lane], acc);
    int s, d;
    if (ge < EE) { s = ei[ge]; d = ei[EE + ge]; }
    else         { s = d = ge - EE; }
    float sv = acc + g_xl2[(size_t)s * D2 + lane] + g_xr2[(size_t)d * D2 + lane];
    sv = (sv > 0.f) ? sv : 0.2f * sv;
    float p = sv * att2[lane];
    #pragma unroll
    for (int o = 16; o > 0; o >>= 1)
        p += __shfl_down_sync(0xffffffffu, p, o);
    if (lane == 0) g_logits2[ge] = p;
}

// ---------------- layer-2 softmax + aggregation + bias + relu -> output ----------------
__global__ __launch_bounds__(256)
void agg2_kernel(const int* __restrict__ ei, const float* __restrict__ b2,
                 float* __restrict__ out)
{
    const int lane = threadIdx.x & 31, w = threadIdx.x >> 5;
    const int n = blockIdx.x * 8 + w;
    if (n >= NN) return;
    const int beg = g_rowptr[n], end = g_rowptr[n + 1];
    float m = g_logits2[EE + n];
    for (int p = beg; p < end; p++) m = fmaxf(m, g_logits2[g_eids[p]]);
    float den = __expf(g_logits2[EE + n] - m);
    for (int p = beg; p < end; p++) den += __expf(g_logits2[g_eids[p]] - m);
    float inv = 1.0f / den;
    float acc = 0.0f;
    for (int p = beg; p <= end; p++) {
        int e, s;
        if (p < end) { e = g_eids[p]; s = ei[e]; }
        else         { e = EE + n;    s = n; }
        float a = __expf(g_logits2[e] - m) * inv;
        acc = fmaf(a, g_xl2[(size_t)s * D2 + lane], acc);
    }
    out[(size_t)n * D2 + lane] = fmaxf(acc + b2[lane], 0.0f);
}

// ---------------- launch ----------------
extern "C" void kernel_launch(void* const* d_in, const int* in_sizes, int n_in,
                              void* d_out, int out_size)
{
    const float* x    = (const float*)d_in[0];
    const int*   ei   = (const int*)d_in[1];
    const float* ea   = (const float*)d_in[2];
    const float* Wl1  = (const float*)d_in[3];
    const float* bl1  = (const float*)d_in[4];
    const float* Wr1  = (const float*)d_in[5];
    const float* br1  = (const float*)d_in[6];
    const float* We1  = (const float*)d_in[7];
    const float* att1 = (const float*)d_in[8];
    const float* b1   = (const float*)d_in[9];
    const float* Wl2  = (const float*)d_in[10];
    const float* bl2  = (const float*)d_in[11];
    const float* Wr2  = (const float*)d_in[12];
    const float* br2  = (const float*)d_in[13];
    const float* We2  = (const float*)d_in[14];
    const float* att2 = (const float*)d_in[15];
    const float* b2   = (const float*)d_in[16];
    float* out = (float*)d_out;

    int n1 = FIN * D1;                  // 262144
    int n2 = D1 * 32;                   // 65536

    zero_cnt_kernel<<<(NN + 255) / 256, 256>>>();                       // 1
    pack_kernel<<<(n1 + 255) / 256, 256>>>(Wl1, FIN, D1, 0, D1, 1);     // 2
    pack_kernel<<<(n1 + 255) / 256, 256>>>(Wr1, FIN, D1, 0, D1, 2);     // 3
    pack_kernel<<<(n1 + 255) / 256, 256>>>(We1, FIN, D1, 0, D1, 0);     // 4

    dim3 gproj((NN + 63) / 64, 32);
    proj1_tc<<<gproj, 256>>>(x, bl1, br1);                              // 5

    count_kernel<<<(EE + 255) / 256, 256>>>(ei);                        // 6
    pack_kernel<<<(n2 + 255) / 256, 256>>>(Wl2, D1, 64, 0, 32, 3);
    pack_kernel<<<(n2 + 255) / 256, 256>>>(Wr2, D1, 64, 32, 32, 3);
    scan_kernel<<<1, 1024>>>();
    scatter_kernel<<<(EE + 255) / 256, 256>>>(ei);
    selfattr_kernel<<<NN, 128>>>(ea);

    dim3 gedge((ETOT + 63) / 64, H1);
    edge_logits1_tc<<<gedge, 256>>>(ea, ei, att1);

    agg1_kernel<<<NN, 256>>>(ei, b1);

    proj2_tc<<<(NN + 63) / 64, 256>>>(bl2, br2);
    edge_logits2_kernel<<<(ETOT + 3) / 4, 128>>>(ea, ei, We2, att2);
    agg2_kernel<<<(NN + 7) / 8, 256>>>(ei, b2, out);
}

// round 13
// speedup vs baseline: 1.0367x; 1.0367x over previous
#include <cuda_runtime.h>
#include <cstdint>

#define NN   10000
#define EE   80000
#define ETOT 90000
#define FIN  128
#define D1   2048
#define H1   8
#define C1   256
#define D2   32

// ---------------- scratch (static __device__, no allocations) ----------------
__device__ float g_self[(size_t)NN * FIN];        // self-loop edge attrs (mean)
__device__ float g_xl1[(size_t)NN * D1];
__device__ float g_xr1[(size_t)NN * D1];
__device__ float g_h[(size_t)NN * D1];
__device__ float g_logits[(size_t)ETOT * H1];
__device__ float g_xl2[(size_t)NN * D2];
__device__ float g_xr2[(size_t)NN * D2];
__device__ float g_logits2[ETOT];
// fragment-order packed, tf32-rounded weight buffers
__device__ float g_Wl1hi[(size_t)FIN * D1];
__device__ float g_Wl1lo[(size_t)FIN * D1];
__device__ float g_Wr1hi[(size_t)FIN * D1];
__device__ float g_Wr1lo[(size_t)FIN * D1];
__device__ float g_We1p[(size_t)FIN * D1];
__device__ float g_W2hi[(size_t)D1 * 64];
__device__ float g_W2lo[(size_t)D1 * 64];
__device__ int   g_cnt[NN];
__device__ int   g_rowptr[NN + 1];
__device__ int   g_cursor[NN];
__device__ int   g_eids[EE];

__device__ __forceinline__ float to_tf32(float x) {
    float r;
    asm("cvt.rna.tf32.f32 %0, %1;" : "=f"(r) : "f"(x));
    return r;
}

__device__ __forceinline__ void mma_tf32(float* c,
                                         float a0, float a1, float a2, float a3,
                                         float b0, float b1)
{
    asm volatile(
        "mma.sync.aligned.m16n8k8.row.col.f32.tf32.tf32.f32 "
        "{%0,%1,%2,%3}, {%4,%5,%6,%7}, {%8,%9}, {%0,%1,%2,%3};"
        : "+f"(c[0]), "+f"(c[1]), "+f"(c[2]), "+f"(c[3])
        : "r"(__float_as_uint(a0)), "r"(__float_as_uint(a1)),
          "r"(__float_as_uint(a2)), "r"(__float_as_uint(a3)),
          "r"(__float_as_uint(b0)), "r"(__float_as_uint(b1)));
}

// ---------------- CSR construction ----------------
__global__ void zero_cnt_kernel() {
    int i = blockIdx.x * 256 + threadIdx.x;
    if (i < NN) g_cnt[i] = 0;
}

__global__ void count_kernel(const int* __restrict__ ei) {
    int e = blockIdx.x * 256 + threadIdx.x;
    if (e < EE) atomicAdd(&g_cnt[ei[EE + e]], 1);
}

__global__ void scan_kernel() {
    __shared__ int sd[1024];
    __shared__ int carry;
    int tid = threadIdx.x;
    if (tid == 0) carry = 0;
    __syncthreads();
    for (int base = 0; base < NN; base += 1024) {
        int i = base + tid;
        int v = (i < NN) ? g_cnt[i] : 0;
        sd[tid] = v;
        __syncthreads();
        for (int off = 1; off < 1024; off <<= 1) {
            int t = (tid >= off) ? sd[tid - off] : 0;
            __syncthreads();
            sd[tid] += t;
            __syncthreads();
        }
        int excl = sd[tid] - v + carry;
        if (i < NN) { g_rowptr[i] = excl; g_cursor[i] = excl; }
        __syncthreads();
        if (tid == 1023) carry += sd[1023];
        __syncthreads();
    }
    if (tid == 0) g_rowptr[NN] = carry;
}

__global__ void scatter_kernel(const int* __restrict__ ei) {
    int e = blockIdx.x * 256 + threadIdx.x;
    if (e < EE) {
        int d = ei[EE + e];
        int pos = atomicAdd(&g_cursor[d], 1);
        g_eids[pos] = e;
    }
}

// ---------------- self-loop attr = mean of incoming edge attrs ----------------
__global__ void selfattr_kernel(const float* __restrict__ ea) {
    int n = blockIdx.x;
    int tid = threadIdx.x;  // 128 threads = FIN
    int beg = g_rowptr[n], end = g_rowptr[n + 1];
    float s = 0.0f;
    for (int p = beg; p < end; p++)
        s += ea[(size_t)g_eids[p] * FIN + tid];
    float c = (float)((end - beg) > 1 ? (end - beg) : 1);
    g_self[(size_t)n * FIN + tid] = s / c;
}

// ---------------- fragment-order weight packing (device-side destinations) --------
// flat = ((((chunk*NW + wn)*4 + n)*8 + g)*4 + c)*4 + j  for k = chunk*16 + c + 4j,
// col = wn*32 + n*8 + g, NW = Ntot/32.
// dst: 0=We1p(hi only) 1=Wl1 2=Wr1(hi only) 3=W2(colOff)
__global__ void pack_kernel(const float* __restrict__ W, int K, int Ntot,
                            int colOff, int Ncols, int dst)
{
    int i = blockIdx.x * 256 + threadIdx.x;
    if (i >= K * Ncols) return;
    int k = i / Ncols, cl = i % Ncols;
    int gc = colOff + cl;
    int chunk = k >> 4;
    int c = k & 3, j = (k & 15) >> 2;
    int wn = gc >> 5, n = (gc >> 3) & 3, g = gc & 7;
    size_t flat = ((((size_t)(chunk * (Ntot >> 5) + wn) * 4 + n) * 8 + g) * 4 + c) * 4 + j;
    float w = W[i];
    float h = to_tf32(w);
    float l = to_tf32(w - h);
    if (dst == 0)      { g_We1p[flat] = h; }
    else if (dst == 1) { g_Wl1hi[flat] = h; g_Wl1lo[flat] = l; }
    else if (dst == 2) { g_Wr1hi[flat] = h; }
    else               { g_W2hi[flat] = h;  g_W2lo[flat] = l; }
}

// ---------------- layer-1 node projection, tf32 MMA, packed B ----------------
// BM=64, BN=128, K=128. grid.y in [0,32): y<16 -> Wl1 (split-tf32, value path),
// y>=16 -> Wr1 (plain tf32 — feeds logits only).
__global__ __launch_bounds__(256)
void proj1_tc(const float* __restrict__ x,
              const float* __restrict__ bl1, const float* __restrict__ br1)
{
    __shared__ float As[64 * 144];     // raw fp32, k-permuted + XOR-swizzled
    const int tid = threadIdx.x;
    const int lane = tid & 31;
    const int warp = tid >> 5;
    const int warp_m = warp & 1;
    const int warp_n = warp >> 1;
    const int g = lane >> 2;
    const int c = lane & 3;
    const int blockRow = blockIdx.x * 64;
    const int ymat = blockIdx.y >> 4;
    const int cbm = (blockIdx.y & 15) * 128;

    const float4* __restrict__ Bh = (const float4*)(ymat ? g_Wr1hi : g_Wl1hi);
    const float4* __restrict__ Bl = (const float4*)g_Wl1lo;
    const float* __restrict__ bias = ymat ? br1 : bl1;
    float* __restrict__ C = ymat ? g_xr1 : g_xl1;

    {
        int row = tid >> 2;
        int gr = blockRow + row; if (gr > NN - 1) gr = NN - 1;
        const float4* ap = (const float4*)(x + (size_t)gr * FIN);
        int rs = row & 3;
        #pragma unroll
        for (int i = 0; i < 8; i++) {
            int q = (tid & 3) + i * 4;
            float4 v = ap[q];
            int base = row * 144 + i * 16 + (tid & 3);
            As[base + ((0 ^ rs) << 2)] = v.x;
            As[base + ((1 ^ rs) << 2)] = v.y;
            As[base + ((2 ^ rs) << 2)] = v.z;
            As[base + ((3 ^ rs) << 2)] = v.w;
        }
    }
    __syncthreads();

    float cc[2][4][4];
    #pragma unroll
    for (int m = 0; m < 2; m++)
        #pragma unroll
        for (int n = 0; n < 4; n++)
            #pragma unroll
            for (int j = 0; j < 4; j++) cc[m][n][j] = 0.0f;

    const int wn = (cbm >> 5) + warp_n;
    const int cswz = ((c ^ (g & 3)) << 2);

    if (ymat == 0) {
        // split-tf32: hi*hi + hi*lo + lo*hi (value path, effectively fp32)
        #pragma unroll
        for (int chunk = 0; chunk < 8; chunk++) {
            float4 vh[2][2], vl[2][2];
            #pragma unroll
            for (int m = 0; m < 2; m++) {
                int col = (warp_m * 32 + m * 16 + g) * 144 + chunk * 16 + cswz;
                #pragma unroll
                for (int hh = 0; hh < 2; hh++) {
                    float4 raw = *(const float4*)(As + col + hh * (8 * 144));
                    float4 h, l;
                    h.x = to_tf32(raw.x); l.x = to_tf32(raw.x - h.x);
                    h.y = to_tf32(raw.y); l.y = to_tf32(raw.y - h.y);
                    h.z = to_tf32(raw.z); l.z = to_tf32(raw.z - h.z);
                    h.w = to_tf32(raw.w); l.w = to_tf32(raw.w - h.w);
                    vh[m][hh] = h; vl[m][hh] = l;
                }
            }
            size_t base4 = ((size_t)(chunk * 64 + wn) * 32 + g) * 4 + c;
            float4 bh[4], bo[4];
            #pragma unroll
            for (int n = 0; n < 4; n++) {
                bh[n] = Bh[base4 + n * 32];
                bo[n] = Bl[base4 + n * 32];
            }
            #pragma unroll
            for (int n = 0; n < 4; n++) {
                #pragma unroll
                for (int m = 0; m < 2; m++) {
                    mma_tf32(cc[m][n], vh[m][0].x, vh[m][1].x, vh[m][0].y, vh[m][1].y, bh[n].x, bh[n].y);
                    mma_tf32(cc[m][n], vh[m][0].x, vh[m][1].x, vh[m][0].y, vh[m][1].y, bo[n].x, bo[n].y);
                    mma_tf32(cc[m][n], vl[m][0].x, vl[m][1].x, vl[m][0].y, vl[m][1].y, bh[n].x, bh[n].y);
                    mma_tf32(cc[m][n], vh[m][0].z, vh[m][1].z, vh[m][0].w, vh[m][1].w, bh[n].z, bh[n].w);
                    mma_tf32(cc[m][n], vh[m][0].z, vh[m][1].z, vh[m][0].w, vh[m][1].w, bo[n].z, bo[n].w);
                    mma_tf32(cc[m][n], vl[m][0].z, vl[m][1].z, vl[m][0].w, vl[m][1].w, bh[n].z, bh[n].w);
                }
            }
        }
    } else {
        // plain tf32: xr1 feeds logits only
        #pragma unroll
        for (int chunk = 0; chunk < 8; chunk++) {
            float4 vh[2][2];
            #pragma unroll
            for (int m = 0; m < 2; m++) {
                int col = (warp_m * 32 + m * 16 + g) * 144 + chunk * 16 + cswz;
                #pragma unroll
                for (int hh = 0; hh < 2; hh++) {
                    float4 raw = *(const float4*)(As + col + hh * (8 * 144));
                    float4 h;
                    h.x = to_tf32(raw.x); h.y = to_tf32(raw.y);
                    h.z = to_tf32(raw.z); h.w = to_tf32(raw.w);
                    vh[m][hh] = h;
                }
            }
            size_t base4 = ((size_t)(chunk * 64 + wn) * 32 + g) * 4 + c;
            float4 bh[4];
            #pragma unroll
            for (int n = 0; n < 4; n++)
                bh[n] = Bh[base4 + n * 32];
            #pragma unroll
            for (int n = 0; n < 4; n++) {
                #pragma unroll
                for (int m = 0; m < 2; m++) {
                    mma_tf32(cc[m][n], vh[m][0].x, vh[m][1].x, vh[m][0].y, vh[m][1].y, bh[n].x, bh[n].y);
                    mma_tf32(cc[m][n], vh[m][0].z, vh[m][1].z, vh[m][0].w, vh[m][1].w, bh[n].z, bh[n].w);
                }
            }
        }
    }

    #pragma unroll
    for (int n = 0; n < 4; n++) {
        int col = cbm + warp_n * 32 + n * 8 + c * 2;
        float2 bv = *(const float2*)(bias + col);
        #pragma unroll
        for (int m = 0; m < 2; m++) {
            #pragma unroll
            for (int hh = 0; hh < 2; hh++) {
                int r = blockRow + warp_m * 32 + m * 16 + hh * 8 + g;
                if (r < NN) {
                    float2 o;
                    o.x = cc[m][n][hh * 2 + 0] + bv.x;
                    o.y = cc[m][n][hh * 2 + 1] + bv.y;
                    *(float2*)(C + (size_t)r * D1 + col) = o;
                }
            }
        }
    }
}

// ---------------- fused edge GEMM + GATv2 logits (layer 1) ----------------
// grid = (1407, 8): one head per block, loop over that head's 2 column blocks.
// Logits reduced block-locally (shuffle + smem) and stored once — no atomics.
__global__ __launch_bounds__(256)
void edge_logits1_tc(const float* __restrict__ ea, const int* __restrict__ ei,
                     const float* __restrict__ att)
{
    __shared__ float As[64 * 144];
    __shared__ float sm_red[4][64];    // [warp_n][row]
    const int tid = threadIdx.x;
    const int lane = tid & 31;
    const int warp = tid >> 5;
    const int warp_m = warp & 1;
    const int warp_n = warp >> 1;
    const int g = lane >> 2;
    const int c = lane & 3;
    const int blockRow = blockIdx.x * 64;
    const int head = blockIdx.y;

    {
        int row = tid >> 2;
        int ge = blockRow + row; if (ge > ETOT - 1) ge = ETOT - 1;
        const float4* ap = (ge < EE) ? (const float4*)(ea + (size_t)ge * FIN)
                                     : (const float4*)(g_self + (size_t)(ge - EE) * FIN);
        int rs = row & 3;
        #pragma unroll
        for (int i = 0; i < 8; i++) {
            int q = (tid & 3) + i * 4;
            float4 v = ap[q];
            int base = row * 144 + (q >> 2) * 16 + (q & 3);
            As[base + ((0 ^ rs) << 2)] = to_tf32(v.x);
            As[base + ((1 ^ rs) << 2)] = to_tf32(v.y);
            As[base + ((2 ^ rs) << 2)] = to_tf32(v.z);
            As[base + ((3 ^ rs) << 2)] = to_tf32(v.w);
        }
    }
    __syncthreads();

    // hoist per-(m,h) edge ids and src/dst
    int ges[2][2], srcs[2][2], dsts[2][2];
    bool valids[2][2];
    #pragma unroll
    for (int m = 0; m < 2; m++) {
        #pragma unroll
        for (int h = 0; h < 2; h++) {
            int ge = blockRow + warp_m * 32 + m * 16 + h * 8 + g;
            ges[m][h] = ge;
            valids[m][h] = (ge < ETOT);
            int s = 0, d = 0;
            if (ge < EE)       { s = ei[ge]; d = ei[EE + ge]; }
            else if (ge < ETOT){ s = d = ge - EE; }
            srcs[m][h] = s; dsts[m][h] = d;
        }
    }

    const int cswz = ((c ^ (g & 3)) << 2);
    const float4* __restrict__ Bp = (const float4*)g_We1p;

    float pacc[2][2] = {{0.0f, 0.0f}, {0.0f, 0.0f}};

    #pragma unroll
    for (int half = 0; half < 2; half++) {
        const int cbi = head * 2 + half;
        const int cb = cbi * 128;
        const int wn = cbi * 4 + warp_n;

        float cc[2][4][4];
        #pragma unroll
        for (int m = 0; m < 2; m++)
            #pragma unroll
            for (int n = 0; n < 4; n++)
                #pragma unroll
                for (int j = 0; j < 4; j++) cc[m][n][j] = 0.0f;

        #pragma unroll
        for (int chunk = 0; chunk < 8; chunk++) {
            float4 va[2][2];
            #pragma unroll
            for (int m = 0; m < 2; m++) {
                int col = (warp_m * 32 + m * 16 + g) * 144 + chunk * 16 + cswz;
                va[m][0] = *(const float4*)(As + col);
                va[m][1] = *(const float4*)(As + col + 8 * 144);
            }
            size_t base4 = ((size_t)(chunk * 64 + wn) * 32 + g) * 4 + c;
            float4 bf[4];
            #pragma unroll
            for (int n = 0; n < 4; n++)
                bf[n] = Bp[base4 + n * 32];
            #pragma unroll
            for (int n = 0; n < 4; n++) {
                #pragma unroll
                for (int m = 0; m < 2; m++) {
                    mma_tf32(cc[m][n], va[m][0].x, va[m][1].x, va[m][0].y, va[m][1].y, bf[n].x, bf[n].y);
                    mma_tf32(cc[m][n], va[m][0].z, va[m][1].z, va[m][0].w, va[m][1].w, bf[n].z, bf[n].w);
                }
            }
        }

        float2 attv[4];
        #pragma unroll
        for (int n = 0; n < 4; n++)
            attv[n] = *(const float2*)(att + cb + warp_n * 32 + n * 8 + c * 2);

        #pragma unroll
        for (int m = 0; m < 2; m++) {
            #pragma unroll
            for (int h = 0; h < 2; h++) {
                if (valids[m][h]) {
                    const float* xlp = g_xl1 + (size_t)srcs[m][h] * D1 + cb;
                    const float* xrp = g_xr1 + (size_t)dsts[m][h] * D1 + cb;
                    float p = pacc[m][h];
                    #pragma unroll
                    for (int n = 0; n < 4; n++) {
                        int cl = warp_n * 32 + n * 8 + c * 2;
                        float2 xv = *(const float2*)(xlp + cl);
                        float2 rv = *(const float2*)(xrp + cl);
                        float t0 = cc[m][n][h * 2 + 0] + xv.x + rv.x;
                        float t1 = cc[m][n][h * 2 + 1] + xv.y + rv.y;
                        t0 = (t0 > 0.f) ? t0 : 0.2f * t0;
                        t1 = (t1 > 0.f) ? t1 : 0.2f * t1;
                        p = fmaf(t0, attv[n].x, p);
                        p = fmaf(t1, attv[n].y, p);
                    }
                    pacc[m][h] = p;
                }
            }
        }
    }

    // block-local reduction: warp shuffle over c lanes, then cross-warp_n via smem
    #pragma unroll
    for (int m = 0; m < 2; m++) {
        #pragma unroll
        for (int h = 0; h < 2; h++) {
            float p = pacc[m][h];
            p += __shfl_xor_sync(0xffffffffu, p, 1);
            p += __shfl_xor_sync(0xffffffffu, p, 2);
            if (c == 0)
                sm_red[warp_n][warp_m * 32 + m * 16 + h * 8 + g] = p;
        }
    }
    __syncthreads();
    if (tid < 64) {
        int ge = blockRow + tid;
        if (ge < ETOT) {
            float p = sm_red[0][tid] + sm_red[1][tid]
                    + sm_red[2][tid] + sm_red[3][tid];
            g_logits[(size_t)ge * H1 + head] = p;
        }
    }
}

// ---------------- layer-1 segment softmax + aggregation + bias + relu ----------------
__global__ __launch_bounds__(256)
void agg1_kernel(const int* __restrict__ ei, const float* __restrict__ b1)
{
    const int n = blockIdx.x, tid = threadIdx.x;
    __shared__ float mx[H1], inv[H1];
    const int beg = g_rowptr[n], end = g_rowptr[n + 1];
    if (tid < H1) {
        float m = g_logits[(size_t)(EE + n) * H1 + tid];
        for (int p = beg; p < end; p++)
            m = fmaxf(m, g_logits[(size_t)g_eids[p] * H1 + tid]);
        float s = __expf(g_logits[(size_t)(EE + n) * H1 + tid] - m);
        for (int p = beg; p < end; p++)
            s += __expf(g_logits[(size_t)g_eids[p] * H1 + tid] - m);
        mx[tid] = m;
        inv[tid] = 1.0f / s;
    }
    __syncthreads();
    float acc[8];
    #pragma unroll
    for (int j = 0; j < 8; j++) acc[j] = 0.0f;
    for (int p = beg; p <= end; p++) {
        int e, s;
        if (p < end) { e = g_eids[p]; s = ei[e]; }
        else         { e = EE + n;    s = n; }
        const float* lr = g_logits + (size_t)e * H1;
        const float* xp = g_xl1 + (size_t)s * D1 + tid;
        #pragma unroll
        for (int j = 0; j < 8; j++) {
            float a = __expf(lr[j] - mx[j]) * inv[j];
            acc[j] = fmaf(a, xp[j * 256], acc[j]);
        }
    }
    #pragma unroll
    for (int j = 0; j < 8; j++) {
        int col = j * 256 + tid;
        g_h[(size_t)n * D1 + col] = fmaxf(acc[j] + b1[col], 0.0f);
    }
}

// ---------------- layer-2 projections, split-tf32 MMA, packed B ----------------
__global__ __launch_bounds__(256)
void proj2_tc(const float* __restrict__ bl2, const float* __restrict__ br2)
{
    __shared__ float As2[64 * 20];     // raw fp32, k-permuted
    const int tid = threadIdx.x;
    const int lane = tid & 31;
    const int warp = tid >> 5;
    const int warp_m = warp & 3;
    const int warp_n = warp >> 2;
    const int g = lane >> 2;
    const int c = lane & 3;
    const int blockRow = blockIdx.x * 64;

    const int arow = tid >> 2;
    const int aq = tid & 3;
    int gr = blockRow + arow; if (gr > NN - 1) gr = NN - 1;
    const float* aptr = g_h + (size_t)gr * D1 + aq * 4;

    const float4* __restrict__ Bh = (const float4*)g_W2hi;
    const float4* __restrict__ Bl = (const float4*)g_W2lo;

    float cc[4][4];
    #pragma unroll
    for (int n = 0; n < 4; n++)
        #pragma unroll
        for (int j = 0; j < 4; j++) cc[n][j] = 0.0f;

    float4 v = *(const float4*)(aptr);
    for (int chunk = 0; chunk < 128; chunk++) {
        As2[arow * 20 + 0 * 4 + aq] = v.x;
        As2[arow * 20 + 1 * 4 + aq] = v.y;
        As2[arow * 20 + 2 * 4 + aq] = v.z;
        As2[arow * 20 + 3 * 4 + aq] = v.w;
        __syncthreads();
        if (chunk < 127) v = *(const float4*)(aptr + (chunk + 1) * 16);

        float4 r0 = *(const float4*)(As2 + (warp_m * 16 + g) * 20 + c * 4);
        float4 r1 = *(const float4*)(As2 + (warp_m * 16 + g + 8) * 20 + c * 4);
        float4 h0, l0, h1, l1;
        h0.x = to_tf32(r0.x); l0.x = to_tf32(r0.x - h0.x);
        h0.y = to_tf32(r0.y); l0.y = to_tf32(r0.y - h0.y);
        h0.z = to_tf32(r0.z); l0.z = to_tf32(r0.z - h0.z);
        h0.w = to_tf32(r0.w); l0.w = to_tf32(r0.w - h0.w);
        h1.x = to_tf32(r1.x); l1.x = to_tf32(r1.x - h1.x);
        h1.y = to_tf32(r1.y); l1.y = to_tf32(r1.y - h1.y);
        h1.z = to_tf32(r1.z); l1.z = to_tf32(r1.z - h1.z);
        h1.w = to_tf32(r1.w); l1.w = to_tf32(r1.w - h1.w);

        size_t base4 = ((size_t)(chunk * 2 + warp_n) * 32 + g) * 4 + c;
        #pragma unroll
        for (int n = 0; n < 4; n++) {
            float4 bh = Bh[base4 + n * 32];
            float4 bo = Bl[base4 + n * 32];
            mma_tf32(cc[n], h0.x, h1.x, h0.y, h1.y, bh.x, bh.y);
            mma_tf32(cc[n], h0.x, h1.x, h0.y, h1.y, bo.x, bo.y);
            mma_tf32(cc[n], l0.x, l1.x, l0.y, l1.y, bh.x, bh.y);
            mma_tf32(cc[n], h0.z, h1.z, h0.w, h1.w, bh.z, bh.w);
            mma_tf32(cc[n], h0.z, h1.z, h0.w, h1.w, bo.z, bo.w);
            mma_tf32(cc[n], l0.z, l1.z, l0.w, l1.w, bh.z, bh.w);
        }
        __syncthreads();
    }

    #pragma unroll
    for (int n = 0; n < 4; n++) {
        int col = warp_n * 32 + n * 8 + c * 2;       // 0..63
        int lc = col & 31;
        const float* bias = (col < 32) ? bl2 : br2;
        float* C = (col < 32) ? g_xl2 : g_xr2;
        float2 bv = *(const float2*)(bias + lc);
        #pragma unroll
        for (int hh = 0; hh < 2; hh++) {
            int r = blockRow + warp_m * 16 + hh * 8 + g;
            if (r < NN) {
                float2 o;
                o.x = cc[n][hh * 2 + 0] + bv.x;
                o.y = cc[n][hh * 2 + 1] + bv.y;
                *(float2*)(C + (size_t)r * D2 + lc) = o;
            }
        }
    }
}

// ---------------- layer-2 edge logits ----------------
__global__ __launch_bounds__(128)
void edge_logits2_kernel(const float* __restrict__ ea, const int* __restrict__ ei,
                         const float* __restrict__ We2, const float* __restrict__ att2)
{
    __shared__ float sm[4][FIN];
    const int lane = threadIdx.x & 31, w = threadIdx.x >> 5;
    const int ge = blockIdx.x * 4 + w;
    if (ge >= ETOT) return;
    const float* arow = (ge < EE) ? (ea + (size_t)ge * FIN)
                                  : (g_self + (size_t)(ge - EE) * FIN);
    sm[w][lane]      = arow[lane];
    sm[w][lane + 32] = arow[lane + 32];
    sm[w][lane + 64] = arow[lane + 64];
    sm[w][lane + 96] = arow[lane + 96];
    __syncwarp();
    float acc = 0.0f;
    #pragma unroll 8
    for (int k = 0; k < FIN; k++)
        acc = fmaf(sm[w][k], We2[(size_t)k * D2 + lane], acc);
    int s, d;
    if (ge < EE) { s = ei[ge]; d = ei[EE + ge]; }
    else         { s = d = ge - EE; }
    float sv = acc + g_xl2[(size_t)s * D2 + lane] + g_xr2[(size_t)d * D2 + lane];
    sv = (sv > 0.f) ? sv : 0.2f * sv;
    float p = sv * att2[lane];
    #pragma unroll
    for (int o = 16; o > 0; o >>= 1)
        p += __shfl_down_sync(0xffffffffu, p, o);
    if (lane == 0) g_logits2[ge] = p;
}

// ---------------- layer-2 softmax + aggregation + bias + relu -> output ----------------
__global__ __launch_bounds__(256)
void agg2_kernel(const int* __restrict__ ei, const float* __restrict__ b2,
                 float* __restrict__ out)
{
    const int lane = threadIdx.x & 31, w = threadIdx.x >> 5;
    const int n = blockIdx.x * 8 + w;
    if (n >= NN) return;
    const int beg = g_rowptr[n], end = g_rowptr[n + 1];
    float m = g_logits2[EE + n];
    for (int p = beg; p < end; p++) m = fmaxf(m, g_logits2[g_eids[p]]);
    float den = __expf(g_logits2[EE + n] - m);
    for (int p = beg; p < end; p++) den += __expf(g_logits2[g_eids[p]] - m);
    float inv = 1.0f / den;
    float acc = 0.0f;
    for (int p = beg; p <= end; p++) {
        int e, s;
        if (p < end) { e = g_eids[p]; s = ei[e]; }
        else         { e = EE + n;    s = n; }
        float a = __expf(g_logits2[e] - m) * inv;
        acc = fmaf(a, g_xl2[(size_t)s * D2 + lane], acc);
    }
    out[(size_t)n * D2 + lane] = fmaxf(acc + b2[lane], 0.0f);
}

// ---------------- launch ----------------
extern "C" void kernel_launch(void* const* d_in, const int* in_sizes, int n_in,
                              void* d_out, int out_size)
{
    const float* x    = (const float*)d_in[0];
    const int*   ei   = (const int*)d_in[1];
    const float* ea   = (const float*)d_in[2];
    const float* Wl1  = (const float*)d_in[3];
    const float* bl1  = (const float*)d_in[4];
    const float* Wr1  = (const float*)d_in[5];
    const float* br1  = (const float*)d_in[6];
    const float* We1  = (const float*)d_in[7];
    const float* att1 = (const float*)d_in[8];
    const float* b1   = (const float*)d_in[9];
    const float* Wl2  = (const float*)d_in[10];
    const float* bl2  = (const float*)d_in[11];
    const float* Wr2  = (const float*)d_in[12];
    const float* br2  = (const float*)d_in[13];
    const float* We2  = (const float*)d_in[14];
    const float* att2 = (const float*)d_in[15];
    const float* b2   = (const float*)d_in[16];
    float* out = (float*)d_out;

    int n1 = FIN * D1;                  // 262144
    int n2 = D1 * 32;                   // 65536

    zero_cnt_kernel<<<(NN + 255) / 256, 256>>>();                       // 1
    pack_kernel<<<(n1 + 255) / 256, 256>>>(Wl1, FIN, D1, 0, D1, 1);     // 2
    pack_kernel<<<(n1 + 255) / 256, 256>>>(Wr1, FIN, D1, 0, D1, 2);     // 3
    pack_kernel<<<(n1 + 255) / 256, 256>>>(We1, FIN, D1, 0, D1, 0);     // 4

    dim3 gproj((NN + 63) / 64, 32);
    proj1_tc<<<gproj, 256>>>(x, bl1, br1);                              // 5

    count_kernel<<<(EE + 255) / 256, 256>>>(ei);                        // 6
    pack_kernel<<<(n2 + 255) / 256, 256>>>(Wl2, D1, 64, 0, 32, 3);
    pack_kernel<<<(n2 + 255) / 256, 256>>>(Wr2, D1, 64, 32, 32, 3);
    scan_kernel<<<1, 1024>>>();
    scatter_kernel<<<(EE + 255) / 256, 256>>>(ei);
    selfattr_kernel<<<NN, 128>>>(ea);

    dim3 gedge((ETOT + 63) / 64, H1);
    edge_logits1_tc<<<gedge, 256>>>(ea, ei, att1);

    agg1_kernel<<<NN, 256>>>(ei, b1);

    proj2_tc<<<(NN + 63) / 64, 256>>>(bl2, br2);
    edge_logits2_kernel<<<(ETOT + 3) / 4, 128>>>(ea, ei, We2, att2);
    agg2_kernel<<<(NN + 7) / 8, 256>>>(ei, b2, out);
}